// round 4
// baseline (speedup 1.0000x reference)
#include <cuda_runtime.h>
#include <math.h>

#define NTOK   (4 * 4096)   // B*L = 16384 tokens
#define HIDDIM 1024
#define NH     16
#define HD     64

// Scratch (allocation-free rule: device globals)
__device__ float g_q[(size_t)NTOK * HIDDIM];
__device__ float g_k[(size_t)NTOK * HIDDIM];
__device__ float g_v[(size_t)NTOK * HIDDIM];
__device__ float g_att[(size_t)NTOK * HIDDIM];

// ---------------------------------------------------------------------------
// GEMM: C[M,N] = A[M,K] @ W[K,N] + bias   (M=16384, N=K=1024)
// 128x128 block tile, BK=16, 256 threads, 8x8 register micro-tile per thread.
// ---------------------------------------------------------------------------
#define BM 128
#define BN 128
#define BK 16
#define TM 8
#define TN 8

__global__ __launch_bounds__(256) void gemm_bias_kernel(
    const float* __restrict__ A, const float* __restrict__ W,
    const float* __restrict__ bias, float* __restrict__ C)
{
    const int M = NTOK, N = HIDDIM, K = HIDDIM;
    __shared__ float As[BK][BM];       // k-major A tile (transposed on store)
    __shared__ float Bs[BK][BN];

    const int bm = blockIdx.y * BM;
    const int bn = blockIdx.x * BN;
    const int tid = threadIdx.x;

    // A-tile loads: 128 rows x 16 cols = 512 float4 -> 2 per thread
    const int arow = tid >> 2;           // 0..63
    const int acol = (tid & 3) * 4;      // 0,4,8,12
    // B-tile loads: 16 rows x 128 cols = 512 float4 -> 2 per thread
    const int brow = tid >> 5;           // 0..7
    const int bcol = (tid & 31) * 4;     // 0..124

    const int ty = tid >> 4;             // 0..15 (row group)
    const int tx = tid & 15;             // 0..15 (col group)

    float acc[TM][TN];
    #pragma unroll
    for (int i = 0; i < TM; i++)
        #pragma unroll
        for (int j = 0; j < TN; j++) acc[i][j] = 0.0f;

    for (int k0 = 0; k0 < K; k0 += BK) {
        #pragma unroll
        for (int i = 0; i < 2; i++) {
            int r = arow + i * 64;
            float4 v = *reinterpret_cast<const float4*>(
                &A[(size_t)(bm + r) * K + k0 + acol]);
            As[acol + 0][r] = v.x;
            As[acol + 1][r] = v.y;
            As[acol + 2][r] = v.z;
            As[acol + 3][r] = v.w;
        }
        #pragma unroll
        for (int i = 0; i < 2; i++) {
            int r = brow + i * 8;
            float4 v = *reinterpret_cast<const float4*>(
                &W[(size_t)(k0 + r) * N + bn + bcol]);
            *reinterpret_cast<float4*>(&Bs[r][bcol]) = v;
        }
        __syncthreads();

        #pragma unroll
        for (int kk = 0; kk < BK; kk++) {
            float a[TM], b[TN];
            #pragma unroll
            for (int i = 0; i < TM; i++) a[i] = As[kk][ty * TM + i];
            #pragma unroll
            for (int j = 0; j < TN; j++) b[j] = Bs[kk][tx * TN + j];
            #pragma unroll
            for (int i = 0; i < TM; i++)
                #pragma unroll
                for (int j = 0; j < TN; j++)
                    acc[i][j] += a[i] * b[j];
        }
        __syncthreads();
    }

    #pragma unroll
    for (int i = 0; i < TM; i++) {
        int r = bm + ty * TM + i;
        #pragma unroll
        for (int j = 0; j < TN; j += 4) {
            int c = bn + tx * TN + j;
            float4 v;
            v.x = acc[i][j + 0] + bias[c + 0];
            v.y = acc[i][j + 1] + bias[c + 1];
            v.z = acc[i][j + 2] + bias[c + 2];
            v.w = acc[i][j + 3] + bias[c + 3];
            *reinterpret_cast<float4*>(&C[(size_t)r * N + c]) = v;
        }
    }
}

// ---------------------------------------------------------------------------
// Per-token head-mixing attention.
// scores[h][e] = (q[h]·k[e]) / 8 ; softmax over e ; out[h] = sum_e p[h][e] v[e]
// One block (256 threads) per token.
// ---------------------------------------------------------------------------
__global__ __launch_bounds__(256) void attn_kernel(float* __restrict__ o)
{
    __shared__ float sq[NH][HD + 1];
    __shared__ float sk[NH][HD + 1];
    __shared__ float sv[NH][HD + 1];
    __shared__ float sp[NH][NH];

    const size_t tok = blockIdx.x;
    const float* qp = g_q + tok * HIDDIM;
    const float* kp = g_k + tok * HIDDIM;
    const float* vp = g_v + tok * HIDDIM;
    const int tid = threadIdx.x;

    for (int i = tid; i < HIDDIM; i += 256) {
        int h = i >> 6, d = i & 63;
        sq[h][d] = qp[i];
        sk[h][d] = kp[i];
        sv[h][d] = vp[i];
    }
    __syncthreads();

    // one thread per (h, e) score
    const int h = tid >> 4;
    const int e = tid & 15;
    float s = 0.0f;
    #pragma unroll
    for (int d = 0; d < HD; d++) s += sq[h][d] * sk[e][d];
    s *= 0.125f;  // 1/sqrt(64)

    // softmax over e: reduce within the 16-lane group sharing h
    float m = s;
    #pragma unroll
    for (int off = 8; off > 0; off >>= 1)
        m = fmaxf(m, __shfl_xor_sync(0xffffffffu, m, off));
    float p = __expf(s - m);
    float sum = p;
    #pragma unroll
    for (int off = 8; off > 0; off >>= 1)
        sum += __shfl_xor_sync(0xffffffffu, sum, off);
    sp[h][e] = p / sum;
    __syncthreads();

    for (int idx = tid; idx < HIDDIM; idx += 256) {
        int hh = idx >> 6, d = idx & 63;
        float acc = 0.0f;
        #pragma unroll
        for (int e2 = 0; e2 < NH; e2++) acc += sp[hh][e2] * sv[e2][d];
        o[tok * HIDDIM + idx] = acc;
    }
}

// ---------------------------------------------------------------------------
extern "C" void kernel_launch(void* const* d_in, const int* in_sizes, int n_in,
                              void* d_out, int out_size)
{
    const float* x  = (const float*)d_in[0];
    const float* Wq = (const float*)d_in[1];
    const float* bq = (const float*)d_in[2];
    const float* Wk = (const float*)d_in[3];
    const float* bk = (const float*)d_in[4];
    const float* Wv = (const float*)d_in[5];
    const float* bv = (const float*)d_in[6];
    const float* Wo = (const float*)d_in[7];
    const float* bo = (const float*)d_in[8];
    float* out = (float*)d_out;

    void* pq;  cudaGetSymbolAddress(&pq,  g_q);
    void* pk;  cudaGetSymbolAddress(&pk,  g_k);
    void* pv;  cudaGetSymbolAddress(&pv,  g_v);
    void* pat; cudaGetSymbolAddress(&pat, g_att);

    dim3 grid(HIDDIM / BN, NTOK / BM);
    dim3 blk(256);

    gemm_bias_kernel<<<grid, blk>>>(x, Wq, bq, (float*)pq);
    gemm_bias_kernel<<<grid, blk>>>(x, Wk, bk, (float*)pk);
    gemm_bias_kernel<<<grid, blk>>>(x, Wv, bv, (float*)pv);

    attn_kernel<<<NTOK, 256>>>((float*)pat);

    gemm_bias_kernel<<<grid, blk>>>((float*)pat, Wo, bo, out);
}

// round 8
// speedup vs baseline: 3.2685x; 3.2685x over previous
#include <cuda_runtime.h>
#include <stdint.h>
#include <math.h>

#define NTOK   16384      // B*L
#define HIDDIM 1024
#define NH     16
#define HD     64

// ---------------- scratch (allocation-free rule: device globals) -----------
__device__ float g_xr[(size_t)NTOK * HIDDIM];          // tf32-rounded x
__device__ float g_wr[4][(size_t)HIDDIM * HIDDIM];     // tf32-rounded Wq,Wk,Wv,Wo
__device__ float g_q [(size_t)NTOK * HIDDIM];
__device__ float g_k [(size_t)NTOK * HIDDIM];
__device__ float g_v [(size_t)NTOK * HIDDIM];
__device__ float g_att[(size_t)NTOK * HIDDIM];         // tf32-rounded attn out

__device__ __forceinline__ float tf32_rna(float x) {
    float y;
    asm("cvt.rna.tf32.f32 %0, %1;" : "=f"(y) : "f"(x));
    return y;
}

// ---------------- elementwise tf32 rounding pass ---------------------------
__global__ __launch_bounds__(256) void round_tf32_kernel(
    const float4* __restrict__ in, float4* __restrict__ out, int n4)
{
    for (int i = blockIdx.x * blockDim.x + threadIdx.x; i < n4;
         i += gridDim.x * blockDim.x) {
        float4 v = in[i];
        v.x = tf32_rna(v.x);
        v.y = tf32_rna(v.y);
        v.z = tf32_rna(v.z);
        v.w = tf32_rna(v.w);
        out[i] = v;
    }
}

// ---------------- tf32 tensor-core GEMM ------------------------------------
// C[M,N] = A[M,K] @ W[K,N] + bias ; M=16384, N=K=1024.
// 128x128x32 block tile, 8 warps (warp tile 32x64), mma.m16n8k8.tf32,
// cp.async 2-stage double buffering. Inputs must be pre-rounded to tf32.
#define BM 128
#define BN 128
#define BK 32
#define NTILES (HIDDIM / BK)      // 32
#define ASTRIDE 36                // 32 + 4 pad  -> bank = (4*row+col)%32, conflict-free frags
#define BSTRIDE 136               // 128 + 8 pad -> bank = (8*row+col)%32, conflict-free frags
#define ASZ (BM * ASTRIDE)        // floats
#define BSZ (BK * BSTRIDE)
#define STAGE (ASZ + BSZ)
#define GEMM_SMEM_BYTES (2 * STAGE * 4)   // 71680 B

__device__ __forceinline__ void cp16(uint32_t dst, const void* src) {
    asm volatile("cp.async.cg.shared.global [%0], [%1], 16;\n"
                 :: "r"(dst), "l"(src));
}

__device__ __forceinline__ void mma_tf32(float c[4], const uint32_t a[4],
                                         const uint32_t b[2]) {
    asm volatile(
        "mma.sync.aligned.m16n8k8.row.col.f32.tf32.tf32.f32 "
        "{%0,%1,%2,%3}, {%4,%5,%6,%7}, {%8,%9}, {%0,%1,%2,%3};\n"
        : "+f"(c[0]), "+f"(c[1]), "+f"(c[2]), "+f"(c[3])
        : "r"(a[0]), "r"(a[1]), "r"(a[2]), "r"(a[3]),
          "r"(b[0]), "r"(b[1]));
}

extern __shared__ float g_smem[];

__global__ __launch_bounds__(256, 2) void gemm_tf32_kernel(
    const float* __restrict__ A, const float* __restrict__ W,
    const float* __restrict__ bias, float* __restrict__ C)
{
    const int bm   = blockIdx.y * BM;
    const int bn   = blockIdx.x * BN;
    const int tid  = threadIdx.x;
    const int lane = tid & 31;
    const int warp = tid >> 5;
    const int wm   = (warp & 3) * 32;   // warp row base within block tile
    const int wn   = (warp >> 2) * 64;  // warp col base
    const int g    = lane >> 2;         // 0..7
    const int tg   = lane & 3;          // 0..3

    const uint32_t smem_base = (uint32_t)__cvta_generic_to_shared(g_smem);

    float acc[2][8][4];
    #pragma unroll
    for (int mt = 0; mt < 2; mt++)
        #pragma unroll
        for (int nt = 0; nt < 8; nt++)
            #pragma unroll
            for (int i = 0; i < 4; i++) acc[mt][nt][i] = 0.0f;

    auto load_tile = [&](int kt, int s) {
        const int k0 = kt * BK;
        uint32_t sa = smem_base + (uint32_t)(s * STAGE) * 4u;
        uint32_t sb = sa + ASZ * 4u;
        const float* Ab = A + (size_t)bm * HIDDIM + k0;
        const float* Bb = W + (size_t)k0 * HIDDIM + bn;
        #pragma unroll
        for (int i = 0; i < 4; i++) {
            int c  = tid + i * 256;        // 0..1023
            int r  = c >> 3;               // 128 rows x 8 float4
            int c4 = (c & 7) << 2;
            cp16(sa + (uint32_t)(r * ASTRIDE + c4) * 4u,
                 Ab + (size_t)r * HIDDIM + c4);
        }
        #pragma unroll
        for (int i = 0; i < 4; i++) {
            int c  = tid + i * 256;
            int r  = c >> 5;               // 32 rows x 32 float4
            int c4 = (c & 31) << 2;
            cp16(sb + (uint32_t)(r * BSTRIDE + c4) * 4u,
                 Bb + (size_t)r * HIDDIM + c4);
        }
        asm volatile("cp.async.commit_group;\n");
    };

    load_tile(0, 0);

    for (int t = 0; t < NTILES; t++) {
        asm volatile("cp.async.wait_group 0;\n");
        __syncthreads();
        if (t + 1 < NTILES) load_tile(t + 1, (t + 1) & 1);

        const uint32_t* uA = (const uint32_t*)(g_smem + (t & 1) * STAGE);
        const uint32_t* uB = uA + ASZ;

        #pragma unroll
        for (int kk = 0; kk < BK / 8; kk++) {
            uint32_t af[2][4], bf[8][2];
            #pragma unroll
            for (int mt = 0; mt < 2; mt++) {
                int r0 = wm + mt * 16 + g;
                int kc = kk * 8 + tg;
                af[mt][0] = uA[r0 * ASTRIDE + kc];
                af[mt][1] = uA[(r0 + 8) * ASTRIDE + kc];
                af[mt][2] = uA[r0 * ASTRIDE + kc + 4];
                af[mt][3] = uA[(r0 + 8) * ASTRIDE + kc + 4];
            }
            #pragma unroll
            for (int nt = 0; nt < 8; nt++) {
                int cc = wn + nt * 8 + g;
                int kr = kk * 8 + tg;
                bf[nt][0] = uB[kr * BSTRIDE + cc];
                bf[nt][1] = uB[(kr + 4) * BSTRIDE + cc];
            }
            #pragma unroll
            for (int mt = 0; mt < 2; mt++)
                #pragma unroll
                for (int nt = 0; nt < 8; nt++)
                    mma_tf32(acc[mt][nt], af[mt], bf[nt]);
        }
    }

    // epilogue: c0/c1 -> (row, col..col+1), c2/c3 -> (row+8, ...)
    #pragma unroll
    for (int mt = 0; mt < 2; mt++) {
        int row = bm + wm + mt * 16 + g;
        #pragma unroll
        for (int nt = 0; nt < 8; nt++) {
            int col = bn + wn + nt * 8 + tg * 2;
            float b0 = bias[col], b1 = bias[col + 1];
            float2 v0 = make_float2(acc[mt][nt][0] + b0, acc[mt][nt][1] + b1);
            float2 v1 = make_float2(acc[mt][nt][2] + b0, acc[mt][nt][3] + b1);
            *reinterpret_cast<float2*>(&C[(size_t)row * HIDDIM + col]) = v0;
            *reinterpret_cast<float2*>(&C[(size_t)(row + 8) * HIDDIM + col]) = v1;
        }
    }
}

// ---------------- per-token head-mixing attention --------------------------
// scores[h][e] = (q[h]·k[e])/8 ; softmax over e ; out[h] = sum_e p[h][e] v[e]
// Output rounded to tf32 (it feeds the final tensor-core GEMM).
__global__ __launch_bounds__(256) void attn_kernel(
    const float* __restrict__ q, const float* __restrict__ k,
    const float* __restrict__ v, float* __restrict__ o)
{
    __shared__ float sq[NH][HD + 1];
    __shared__ float sk[NH][HD + 1];
    __shared__ float sv[NH][HD + 1];
    __shared__ float sp[NH][NH];

    const size_t tok = blockIdx.x;
    const float* qp = q + tok * HIDDIM;
    const float* kp = k + tok * HIDDIM;
    const float* vp = v + tok * HIDDIM;
    const int tid = threadIdx.x;

    for (int i = tid; i < HIDDIM; i += 256) {
        int h = i >> 6, d = i & 63;
        sq[h][d] = qp[i];
        sk[h][d] = kp[i];
        sv[h][d] = vp[i];
    }
    __syncthreads();

    const int h = tid >> 4;
    const int e = tid & 15;
    float s = 0.0f;
    #pragma unroll
    for (int d = 0; d < HD; d++) s += sq[h][d] * sk[e][d];
    s *= 0.125f;

    float m = s;
    #pragma unroll
    for (int off = 8; off > 0; off >>= 1)
        m = fmaxf(m, __shfl_xor_sync(0xffffffffu, m, off));
    float p = __expf(s - m);
    float sum = p;
    #pragma unroll
    for (int off = 8; off > 0; off >>= 1)
        sum += __shfl_xor_sync(0xffffffffu, sum, off);
    sp[h][e] = p / sum;
    __syncthreads();

    for (int idx = tid; idx < HIDDIM; idx += 256) {
        int hh = idx >> 6, d = idx & 63;
        float acc = 0.0f;
        #pragma unroll
        for (int e2 = 0; e2 < NH; e2++) acc += sp[hh][e2] * sv[e2][d];
        o[tok * HIDDIM + idx] = tf32_rna(acc);   // pre-round for final GEMM
    }
}

// ---------------------------------------------------------------------------
extern "C" void kernel_launch(void* const* d_in, const int* in_sizes, int n_in,
                              void* d_out, int out_size)
{
    const float* x  = (const float*)d_in[0];
    const float* Wq = (const float*)d_in[1];
    const float* bq = (const float*)d_in[2];
    const float* Wk = (const float*)d_in[3];
    const float* bk = (const float*)d_in[4];
    const float* Wv = (const float*)d_in[5];
    const float* bv = (const float*)d_in[6];
    const float* Wo = (const float*)d_in[7];
    const float* bo = (const float*)d_in[8];
    float* out = (float*)d_out;

    cudaFuncSetAttribute(gemm_tf32_kernel,
                         cudaFuncAttributeMaxDynamicSharedMemorySize,
                         GEMM_SMEM_BYTES);

    void *pxr, *pwr, *pq, *pk, *pv, *pat;
    cudaGetSymbolAddress(&pxr, g_xr);
    cudaGetSymbolAddress(&pwr, g_wr);
    cudaGetSymbolAddress(&pq,  g_q);
    cudaGetSymbolAddress(&pk,  g_k);
    cudaGetSymbolAddress(&pv,  g_v);
    cudaGetSymbolAddress(&pat, g_att);
    float* xr  = (float*)pxr;
    float* wr  = (float*)pwr;   // 4 weight slots of HIDDIM*HIDDIM
    float* q   = (float*)pq;
    float* k   = (float*)pk;
    float* v   = (float*)pv;
    float* att = (float*)pat;

    const int n4x = NTOK * HIDDIM / 4;
    const int n4w = HIDDIM * HIDDIM / 4;
    round_tf32_kernel<<<2048, 256>>>((const float4*)x, (float4*)xr, n4x);
    round_tf32_kernel<<<1024, 256>>>((const float4*)Wq,
                                     (float4*)(wr + 0 * (size_t)HIDDIM * HIDDIM), n4w);
    round_tf32_kernel<<<1024, 256>>>((const float4*)Wk,
                                     (float4*)(wr + 1 * (size_t)HIDDIM * HIDDIM), n4w);
    round_tf32_kernel<<<1024, 256>>>((const float4*)Wv,
                                     (float4*)(wr + 2 * (size_t)HIDDIM * HIDDIM), n4w);
    round_tf32_kernel<<<1024, 256>>>((const float4*)Wo,
                                     (float4*)(wr + 3 * (size_t)HIDDIM * HIDDIM), n4w);

    dim3 grid(HIDDIM / BN, NTOK / BM);   // (8, 128)
    dim3 blk(256);
    gemm_tf32_kernel<<<grid, blk, GEMM_SMEM_BYTES>>>(
        xr, wr + 0 * (size_t)HIDDIM * HIDDIM, bq, q);
    gemm_tf32_kernel<<<grid, blk, GEMM_SMEM_BYTES>>>(
        xr, wr + 1 * (size_t)HIDDIM * HIDDIM, bk, k);
    gemm_tf32_kernel<<<grid, blk, GEMM_SMEM_BYTES>>>(
        xr, wr + 2 * (size_t)HIDDIM * HIDDIM, bv, v);

    attn_kernel<<<NTOK, 256>>>(q, k, v, att);

    gemm_tf32_kernel<<<grid, blk, GEMM_SMEM_BYTES>>>(
        att, wr + 3 * (size_t)HIDDIM * HIDDIM, bo, out);
}